// round 14
// baseline (speedup 1.0000x reference)
#include <cuda_runtime.h>

// PrimalCosAttention: B=4,H=12,N=4096,D=64,E=32
// out layout (floats):
//  attn   [B,H,N,D]  @ 0           (12,582,912)
//  escore [B,H,N,E]  @ 12,582,912  ( 6,291,456)
//  rscore [B,H,N,E]  @ 18,874,368  ( 6,291,456)
//  we0    [H,D,E]    @ 25,165,824  (    24,576)
//  wr0    [H,D,E]    @ 25,190,400  (    24,576)
//  queries[B,H,N,D]  @ 25,214,976  (12,582,912)
//  keys   [B,H,N,D]  @ 37,797,888  (12,582,912)
//  Lambda [H,E]      @ 50,380,800  (       384)

#define TILE_N 64
#define PAD 68        // row stride (floats); 16B-aligned

// row swizzle: element (r,k) stored at column (k + (r&8)) & 63.
// Kills the 2-way bank conflict on A-loads (4-row stride ≡ 16 banks).
__device__ __forceinline__ int SW(int r, int k) { return (k + (r & 8)) & 63; }

// ============================================================================
// Kernel A: phase 1 (L2 normalize) + phase 2 (score GEMM)
// smem: q_s + k_s + sw = 51.2 KB  -> 4 CTAs/SM
// ============================================================================
__global__ __launch_bounds__(256, 4)
void pca_phase12(const float* __restrict__ Q, const float* __restrict__ K,
                 const float* __restrict__ we, const float* __restrict__ wr,
                 float* __restrict__ escore, float* __restrict__ rscore,
                 float* __restrict__ queries, float* __restrict__ keys)
{
    const int H = 12, N = 4096, D = 64, E = 32;

    extern __shared__ float smem[];
    float* q_s = smem;                    // [64][PAD] normalized Q tile (swizzled cols)
    float* k_s = q_s + TILE_N * PAD;      // [64][PAD] normalized K tile (swizzled cols)
    float* sw  = k_s + TILE_N * PAD;      // [64][64]: cols 0..31 = we0[h], 32..63 = wr0[h]

    const int tile = blockIdx.x;
    const int h    = blockIdx.y;
    const int bq   = blockIdx.z;
    const int n0   = tile * TILE_N;
    const int t    = threadIdx.x;
    const int lane = t & 31;
    const int wp   = t >> 5;

    const long base = ((long)(bq * H + h) * N + n0) * D;

    // ---- load phase-2 weights ----
    const float* weh = we + (long)h * D * E;
    const float* wrh = wr + (long)h * D * E;
    for (int i = t; i < 64 * 64; i += 256) {
        int r = i >> 6, c = i & 63;
        sw[i] = (c < 32) ? weh[r * E + c] : wrh[r * E + (c - 32)];
    }

    // ---- phase 1: L2 normalize. Warp: 4 rows/iter, 8 lanes/row, 8 floats/lane.
    {
        const int subrow = lane >> 3;
        const int sub    = lane & 7;
        #pragma unroll
        for (int it = 0; it < 2; ++it) {
            int r = it * 32 + wp * 4 + subrow;
            long g = base + (long)r * D + sub * 8;
            float4 qa = *(const float4*)(Q + g);
            float4 qb = *(const float4*)(Q + g + 4);
            float4 ka = *(const float4*)(K + g);
            float4 kb = *(const float4*)(K + g + 4);
            float sq = qa.x*qa.x + qa.y*qa.y + qa.z*qa.z + qa.w*qa.w
                     + qb.x*qb.x + qb.y*qb.y + qb.z*qb.z + qb.w*qb.w;
            float sk = ka.x*ka.x + ka.y*ka.y + ka.z*ka.z + ka.w*ka.w
                     + kb.x*kb.x + kb.y*kb.y + kb.z*kb.z + kb.w*kb.w;
            #pragma unroll
            for (int o = 4; o > 0; o >>= 1) {
                sq += __shfl_xor_sync(0xffffffffu, sq, o);
                sk += __shfl_xor_sync(0xffffffffu, sk, o);
            }
            float iq = rsqrtf(fmaxf(sq, 1e-24f));
            float ik = rsqrtf(fmaxf(sk, 1e-24f));
            qa.x *= iq; qa.y *= iq; qa.z *= iq; qa.w *= iq;
            qb.x *= iq; qb.y *= iq; qb.z *= iq; qb.w *= iq;
            ka.x *= ik; ka.y *= ik; ka.z *= ik; ka.w *= ik;
            kb.x *= ik; kb.y *= ik; kb.z *= ik; kb.w *= ik;
            int col = (sub * 8 + (r & 8)) & 63;
            *(float4*)(q_s + r * PAD + col)     = qa;
            *(float4*)(q_s + r * PAD + col + 4) = qb;
            *(float4*)(k_s + r * PAD + col)     = ka;
            *(float4*)(k_s + r * PAD + col + 4) = kb;
            *(float4*)(queries + g)     = qa;
            *(float4*)(queries + g + 4) = qb;
            *(float4*)(keys + g)        = ka;
            *(float4*)(keys + g + 4)    = kb;
        }
    }
    __syncthreads();

    // ---- phase 2: score GEMM.  [64 x 64]; cols 0..31 escore (A=qn), 32..63 rscore (A=kn)
    const int tx = (lane & 7) | ((wp & 1) << 3);
    const int ty = (lane >> 3) | ((wp >> 1) << 2);
    const int c0 = tx * 4;
    const int r0 = ty * 4;
    const float* At = (tx < 8) ? q_s : k_s;

    float acc[4][4];
    #pragma unroll
    for (int i = 0; i < 4; ++i)
        #pragma unroll
        for (int jj = 0; jj < 4; ++jj) acc[i][jj] = 0.0f;

    #pragma unroll 4
    for (int kk = 0; kk < 16; ++kk) {
        const int k4 = kk << 2;
        const float4 w0 = *(const float4*)(sw + (k4 + 0) * 64 + c0);
        const float4 w1 = *(const float4*)(sw + (k4 + 1) * 64 + c0);
        const float4 w2 = *(const float4*)(sw + (k4 + 2) * 64 + c0);
        const float4 w3 = *(const float4*)(sw + (k4 + 3) * 64 + c0);
        #pragma unroll
        for (int i = 0; i < 4; ++i) {
            const int r = r0 + i;
            const float4 a = *(const float4*)(At + r * PAD + SW(r, k4));
            acc[i][0] = fmaf(a.x, w0.x, acc[i][0]);
            acc[i][0] = fmaf(a.y, w1.x, acc[i][0]);
            acc[i][0] = fmaf(a.z, w2.x, acc[i][0]);
            acc[i][0] = fmaf(a.w, w3.x, acc[i][0]);
            acc[i][1] = fmaf(a.x, w0.y, acc[i][1]);
            acc[i][1] = fmaf(a.y, w1.y, acc[i][1]);
            acc[i][1] = fmaf(a.z, w2.y, acc[i][1]);
            acc[i][1] = fmaf(a.w, w3.y, acc[i][1]);
            acc[i][2] = fmaf(a.x, w0.z, acc[i][2]);
            acc[i][2] = fmaf(a.y, w1.z, acc[i][2]);
            acc[i][2] = fmaf(a.z, w2.z, acc[i][2]);
            acc[i][2] = fmaf(a.w, w3.z, acc[i][2]);
            acc[i][3] = fmaf(a.x, w0.w, acc[i][3]);
            acc[i][3] = fmaf(a.y, w1.w, acc[i][3]);
            acc[i][3] = fmaf(a.z, w2.w, acc[i][3]);
            acc[i][3] = fmaf(a.w, w3.w, acc[i][3]);
        }
    }

    // write score (escore / rscore); kernel ends here
    {
        const long so = ((long)(bq * H + h) * N + n0) * E;
        float* sout = (tx < 8) ? (escore + so) : (rscore + so);
        const int ce = c0 & 31;
        #pragma unroll
        for (int i = 0; i < 4; ++i) {
            int r = r0 + i;
            *(float4*)(sout + (long)r * E + ce) =
                make_float4(acc[i][0], acc[i][1], acc[i][2], acc[i][3]);
        }
    }
}

// ============================================================================
// Kernel B: phase 3 (attn = score @ W^T + b, * mask)
// smem: sc_s + wt + b + m = 34.4 KB  -> 4 CTAs/SM
// ============================================================================
__global__ __launch_bounds__(256, 4)
void pca_phase3(const float* __restrict__ escore, const float* __restrict__ rscore,
                const float* __restrict__ mask, const float* __restrict__ W,
                const float* __restrict__ bias, float* __restrict__ attn_out)
{
    const int H = 12, N = 4096, D = 64, E = 32;

    extern __shared__ float smem[];
    float* sc_s = smem;                   // [64][PAD] score tile (swizzled cols)
    float* wt   = sc_s + TILE_N * PAD;    // [64][64]: wt[e][d] = W[d][e]
    float* b_s  = wt + 64 * 64;           // [64]
    float* m_s  = b_s + 64;               // [64]

    const int tile = blockIdx.x;
    const int h    = blockIdx.y;
    const int bq   = blockIdx.z;
    const int n0   = tile * TILE_N;
    const int t    = threadIdx.x;
    const int lane = t & 31;
    const int wp   = t >> 5;

    const long base = ((long)(bq * H + h) * N + n0) * D;
    const long so   = ((long)(bq * H + h) * N + n0) * E;

    // ---- stage W^T, bias, mask ----
    for (int i = t; i < 64 * 64; i += 256) {
        int r = i >> 6, c = i & 63;
        wt[i] = W[c * 64 + r];            // wt[e=r][d=c] = W[d][e]
    }
    if (t < 64) {
        b_s[t] = bias[t];
        m_s[t] = mask[(long)bq * N + n0 + t];
    }

    // ---- stage score tile: [64 rows][64 e]; e<32 from escore, e>=32 from rscore.
    for (int i = t; i < 64 * 16; i += 256) {
        int r  = i >> 4;
        int c4 = (i & 15) * 4;
        const float* src = (c4 < 32) ? (escore + so + (long)r * E + c4)
                                     : (rscore + so + (long)r * E + (c4 - 32));
        *(float4*)(sc_s + r * PAD + SW(r, c4)) = *(const float4*)src;
    }
    __syncthreads();

    // ---- GEMM: attn[64 x 64] = sc @ wt + b ----
    const int tx = (lane & 7) | ((wp & 1) << 3);
    const int ty = (lane >> 3) | ((wp >> 1) << 2);
    const int c0 = tx * 4;
    const int r0 = ty * 4;

    float acc2[4][4];
    #pragma unroll
    for (int i = 0; i < 4; ++i) {
        acc2[i][0] = b_s[c0 + 0];
        acc2[i][1] = b_s[c0 + 1];
        acc2[i][2] = b_s[c0 + 2];
        acc2[i][3] = b_s[c0 + 3];
    }

    #pragma unroll 4
    for (int kk = 0; kk < 16; ++kk) {
        const int e4 = kk << 2;
        const float4 w0 = *(const float4*)(wt + (e4 + 0) * 64 + c0);
        const float4 w1 = *(const float4*)(wt + (e4 + 1) * 64 + c0);
        const float4 w2 = *(const float4*)(wt + (e4 + 2) * 64 + c0);
        const float4 w3 = *(const float4*)(wt + (e4 + 3) * 64 + c0);
        #pragma unroll
        for (int i = 0; i < 4; ++i) {
            const int r = r0 + i;
            const float4 a = *(const float4*)(sc_s + r * PAD + SW(r, e4));
            acc2[i][0] = fmaf(a.x, w0.x, acc2[i][0]);
            acc2[i][0] = fmaf(a.y, w1.x, acc2[i][0]);
            acc2[i][0] = fmaf(a.z, w2.x, acc2[i][0]);
            acc2[i][0] = fmaf(a.w, w3.x, acc2[i][0]);
            acc2[i][1] = fmaf(a.x, w0.y, acc2[i][1]);
            acc2[i][1] = fmaf(a.y, w1.y, acc2[i][1]);
            acc2[i][1] = fmaf(a.z, w2.y, acc2[i][1]);
            acc2[i][1] = fmaf(a.w, w3.y, acc2[i][1]);
            acc2[i][2] = fmaf(a.x, w0.z, acc2[i][2]);
            acc2[i][2] = fmaf(a.y, w1.z, acc2[i][2]);
            acc2[i][2] = fmaf(a.z, w2.z, acc2[i][2]);
            acc2[i][2] = fmaf(a.w, w3.z, acc2[i][2]);
            acc2[i][3] = fmaf(a.x, w0.w, acc2[i][3]);
            acc2[i][3] = fmaf(a.y, w1.w, acc2[i][3]);
            acc2[i][3] = fmaf(a.z, w2.w, acc2[i][3]);
            acc2[i][3] = fmaf(a.w, w3.w, acc2[i][3]);
        }
    }

    // store attn_out (apply mask)
    #pragma unroll
    for (int i = 0; i < 4; ++i) {
        int r = r0 + i;
        float m = m_s[r];
        float4 v = make_float4(acc2[i][0] * m, acc2[i][1] * m,
                               acc2[i][2] * m, acc2[i][3] * m);
        *(float4*)(attn_out + base + (long)r * D + c0) = v;
    }
}

extern "C" void kernel_launch(void* const* d_in, const int* in_sizes, int n_in,
                              void* d_out, int out_size)
{
    const float* Q    = (const float*)d_in[0];
    const float* K    = (const float*)d_in[1];
    const float* we   = (const float*)d_in[2];
    const float* wr   = (const float*)d_in[3];
    const float* mask = (const float*)d_in[4];
    const float* W    = (const float*)d_in[5];
    const float* b    = (const float*)d_in[6];
    const float* Lam  = (const float*)d_in[7];

    float* out = (float*)d_out;
    const long nAttn = 4L * 12 * 4096 * 64;   // 12,582,912
    const long nSc   = 4L * 12 * 4096 * 32;   //  6,291,456
    const long nW0   = 12L * 64 * 32;         //     24,576
    float* attn = out;
    float* esc  = attn + nAttn;
    float* rsc  = esc + nSc;
    float* we0o = rsc + nSc;
    float* wr0o = we0o + nW0;
    float* qo   = wr0o + nW0;
    float* ko   = qo + nAttn;
    float* lo   = ko + nAttn;

    // passthrough outputs (we[0], wr[0] are contiguous leading slices; Lambda whole)
    cudaMemcpyAsync(we0o, we,  nW0 * sizeof(float), cudaMemcpyDeviceToDevice);
    cudaMemcpyAsync(wr0o, wr,  nW0 * sizeof(float), cudaMemcpyDeviceToDevice);
    cudaMemcpyAsync(lo,   Lam, 12L * 32 * sizeof(float), cudaMemcpyDeviceToDevice);

    const size_t shA = (size_t)(2 * TILE_N * PAD + 64 * 64) * sizeof(float);           // 51.2 KB
    const size_t shB = (size_t)(TILE_N * PAD + 64 * 64 + 64 + 64) * sizeof(float);     // 34.4 KB
    cudaFuncSetAttribute(pca_phase12, cudaFuncAttributeMaxDynamicSharedMemorySize, (int)shA);
    cudaFuncSetAttribute(pca_phase3,  cudaFuncAttributeMaxDynamicSharedMemorySize, (int)shB);

    dim3 grid(4096 / TILE_N, 12, 4);
    pca_phase12<<<grid, 256, shA>>>(Q, K, we, wr, esc, rsc, qo, ko);
    pca_phase3 <<<grid, 256, shB>>>(esc, rsc, mask, W, b, attn);
}

// round 15
// speedup vs baseline: 1.2372x; 1.2372x over previous
#include <cuda_runtime.h>

// PrimalCosAttention: B=4,H=12,N=4096,D=64,E=32
// out layout (floats):
//  attn   [B,H,N,D]  @ 0           (12,582,912)
//  escore [B,H,N,E]  @ 12,582,912  ( 6,291,456)
//  rscore [B,H,N,E]  @ 18,874,368  ( 6,291,456)
//  we0    [H,D,E]    @ 25,165,824  (    24,576)
//  wr0    [H,D,E]    @ 25,190,400  (    24,576)
//  queries[B,H,N,D]  @ 25,214,976  (12,582,912)
//  keys   [B,H,N,D]  @ 37,797,888  (12,582,912)
//  Lambda [H,E]      @ 50,380,800  (       384)

#define TILE_N 64
#define PAD 68        // row stride (floats) for q/k/score tiles; 16B-aligned
#define WTP 68        // row stride (floats) for transposed-W tile; 16B-aligned

// row swizzle: element (r,k) stored at column (k + (r&8)) & 63.
// Kills the 2-way bank conflict on A-loads (4-row stride ≡ 16 banks).
__device__ __forceinline__ int SW(int r, int k) { return (k + (r & 8)) & 63; }

__global__ __launch_bounds__(256, 3)
void pca_kernel(const float* __restrict__ Q, const float* __restrict__ K,
                const float* __restrict__ we, const float* __restrict__ wr,
                const float* __restrict__ mask, const float* __restrict__ W,
                const float* __restrict__ bias,
                float* __restrict__ attn_out, float* __restrict__ escore,
                float* __restrict__ rscore, float* __restrict__ queries,
                float* __restrict__ keys)
{
    const int H = 12, N = 4096, D = 64, E = 32;

    extern __shared__ float smem[];
    float* q_s  = smem;                    // [64][PAD] normalized Q tile (swizzled cols)
    float* sc_s = smem;                    // ALIAS: score tile reuses q_s after phase 2
    float* k_s  = q_s  + TILE_N * PAD;     // [64][PAD] normalized K tile (swizzled cols)
    float* sw   = k_s  + TILE_N * PAD;     // [64][64]: cols 0..31 = we0[h], 32..63 = wr0[h] (k-major)
    float* wt   = sw   + 64 * 64;          // [64][WTP]: wt[e][d] = W[d][e]  (transposed via smem)
    float* b_s  = wt   + 64 * WTP;         // [64]
    float* m_s  = b_s  + 64;               // [64] mask tile

    const int tile = blockIdx.x;
    const int h    = blockIdx.y;
    const int bq   = blockIdx.z;
    const int n0   = tile * TILE_N;
    const int t    = threadIdx.x;          // 0..255
    const int lane = t & 31;
    const int wp   = t >> 5;               // warp 0..7

    const long base = ((long)(bq * H + h) * N + n0) * D;

    // ---- load weights ----
    // sw: coalesced reads (consecutive threads -> consecutive floats)
    const float* weh = we + (long)h * D * E;
    const float* wrh = wr + (long)h * D * E;
    for (int i = t; i < 64 * 64; i += 256) {
        int r = i >> 6, c = i & 63;
        sw[i] = (c < 32) ? weh[r * E + c] : wrh[r * E + (c - 32)];
    }
    // wt: COALESCED gmem read of W (16KB/CTA, was 128KB of sectors when read
    // transposed), transpose happens on the smem-store side (4-way STS conflict
    // on 16 instrs — negligible one-time cost).
    for (int i = t; i < 64 * 64; i += 256) {
        int d = i >> 6, e = i & 63;        // read W[d][e] coalesced in e
        wt[e * WTP + d] = W[i];
    }
    if (t < 64) {
        b_s[t] = bias[t];
        m_s[t] = mask[(long)bq * N + n0 + t];
    }

    // ---- phase 1: L2 normalize. Warp: 4 rows/iter, 8 lanes/row, 8 floats/lane.
    {
        const int subrow = lane >> 3;
        const int sub    = lane & 7;
        #pragma unroll
        for (int it = 0; it < 2; ++it) {
            int r = it * 32 + wp * 4 + subrow;
            long g = base + (long)r * D + sub * 8;
            float4 qa = *(const float4*)(Q + g);
            float4 qb = *(const float4*)(Q + g + 4);
            float4 ka = *(const float4*)(K + g);
            float4 kb = *(const float4*)(K + g + 4);
            float sq = qa.x*qa.x + qa.y*qa.y + qa.z*qa.z + qa.w*qa.w
                     + qb.x*qb.x + qb.y*qb.y + qb.z*qb.z + qb.w*qb.w;
            float sk = ka.x*ka.x + ka.y*ka.y + ka.z*ka.z + ka.w*ka.w
                     + kb.x*kb.x + kb.y*kb.y + kb.z*kb.z + kb.w*kb.w;
            #pragma unroll
            for (int o = 4; o > 0; o >>= 1) {
                sq += __shfl_xor_sync(0xffffffffu, sq, o);
                sk += __shfl_xor_sync(0xffffffffu, sk, o);
            }
            float iq = rsqrtf(fmaxf(sq, 1e-24f));
            float ik = rsqrtf(fmaxf(sk, 1e-24f));
            qa.x *= iq; qa.y *= iq; qa.z *= iq; qa.w *= iq;
            qb.x *= iq; qb.y *= iq; qb.z *= iq; qb.w *= iq;
            ka.x *= ik; ka.y *= ik; ka.z *= ik; ka.w *= ik;
            kb.x *= ik; kb.y *= ik; kb.z *= ik; kb.w *= ik;
            int col = (sub * 8 + (r & 8)) & 63;
            *(float4*)(q_s + r * PAD + col)     = qa;
            *(float4*)(q_s + r * PAD + col + 4) = qb;
            *(float4*)(k_s + r * PAD + col)     = ka;
            *(float4*)(k_s + r * PAD + col + 4) = kb;
            *(float4*)(queries + g)     = qa;
            *(float4*)(queries + g + 4) = qb;
            *(float4*)(keys + g)        = ka;
            *(float4*)(keys + g + 4)    = kb;
        }
    }
    __syncthreads();

    // ---- phase 2: score GEMM.  [64 x 64]; cols 0..31 escore (A=qn), 32..63 rscore (A=kn)
    // warp shape: 8 tx (32 cols) x 4 ty (16 rows) -> weight LDS = 128B contiguous
    const int tx = (lane & 7) | ((wp & 1) << 3);   // 0..15
    const int ty = (lane >> 3) | ((wp >> 1) << 2); // 0..15
    const int c0 = tx * 4;
    const int r0 = ty * 4;
    const float* At = (tx < 8) ? q_s : k_s;

    float acc[4][4];
    #pragma unroll
    for (int i = 0; i < 4; ++i)
        #pragma unroll
        for (int jj = 0; jj < 4; ++jj) acc[i][jj] = 0.0f;

    #pragma unroll 4
    for (int kk = 0; kk < 16; ++kk) {
        const int k4 = kk << 2;
        const float4 w0 = *(const float4*)(sw + (k4 + 0) * 64 + c0);
        const float4 w1 = *(const float4*)(sw + (k4 + 1) * 64 + c0);
        const float4 w2 = *(const float4*)(sw + (k4 + 2) * 64 + c0);
        const float4 w3 = *(const float4*)(sw + (k4 + 3) * 64 + c0);
        #pragma unroll
        for (int i = 0; i < 4; ++i) {
            const int r = r0 + i;
            const float4 a = *(const float4*)(At + r * PAD + SW(r, k4));
            acc[i][0] = fmaf(a.x, w0.x, acc[i][0]);
            acc[i][0] = fmaf(a.y, w1.x, acc[i][0]);
            acc[i][0] = fmaf(a.z, w2.x, acc[i][0]);
            acc[i][0] = fmaf(a.w, w3.x, acc[i][0]);
            acc[i][1] = fmaf(a.x, w0.y, acc[i][1]);
            acc[i][1] = fmaf(a.y, w1.y, acc[i][1]);
            acc[i][1] = fmaf(a.z, w2.y, acc[i][1]);
            acc[i][1] = fmaf(a.w, w3.y, acc[i][1]);
            acc[i][2] = fmaf(a.x, w0.z, acc[i][2]);
            acc[i][2] = fmaf(a.y, w1.z, acc[i][2]);
            acc[i][2] = fmaf(a.z, w2.z, acc[i][2]);
            acc[i][2] = fmaf(a.w, w3.z, acc[i][2]);
            acc[i][3] = fmaf(a.x, w0.w, acc[i][3]);
            acc[i][3] = fmaf(a.y, w1.w, acc[i][3]);
            acc[i][3] = fmaf(a.z, w2.w, acc[i][3]);
            acc[i][3] = fmaf(a.w, w3.w, acc[i][3]);
        }
    }

    // write score to gmem (escore / rscore) — no smem involved, safe before barrier
    {
        const long so = ((long)(bq * H + h) * N + n0) * E;
        float* sout = (tx < 8) ? (escore + so) : (rscore + so);
        const int ce = c0 & 31;
        #pragma unroll
        for (int i = 0; i < 4; ++i) {
            int r = r0 + i;
            *(float4*)(sout + (long)r * E + ce) =
                make_float4(acc[i][0], acc[i][1], acc[i][2], acc[i][3]);
        }
    }

    // all reads of q_s/k_s are done -> safe to overwrite q_s with the score tile
    __syncthreads();
    #pragma unroll
    for (int i = 0; i < 4; ++i) {
        int r = r0 + i;
        *(float4*)(sc_s + r * PAD + SW(r, c0)) =
            make_float4(acc[i][0], acc[i][1], acc[i][2], acc[i][3]);
    }
    __syncthreads();

    // ---- phase 3: attn = score @ W^T + b, * mask.  [64 x 64], K = 64 (e)
    float acc2[4][4];
    #pragma unroll
    for (int i = 0; i < 4; ++i) {
        acc2[i][0] = b_s[c0 + 0];
        acc2[i][1] = b_s[c0 + 1];
        acc2[i][2] = b_s[c0 + 2];
        acc2[i][3] = b_s[c0 + 3];
    }

    #pragma unroll 4
    for (int kk = 0; kk < 16; ++kk) {
        const int e4 = kk << 2;
        const float4 w0 = *(const float4*)(wt + (e4 + 0) * WTP + c0);
        const float4 w1 = *(const float4*)(wt + (e4 + 1) * WTP + c0);
        const float4 w2 = *(const float4*)(wt + (e4 + 2) * WTP + c0);
        const float4 w3 = *(const float4*)(wt + (e4 + 3) * WTP + c0);
        #pragma unroll
        for (int i = 0; i < 4; ++i) {
            const int r = r0 + i;
            const float4 a = *(const float4*)(sc_s + r * PAD + SW(r, e4));
            acc2[i][0] = fmaf(a.x, w0.x, acc2[i][0]);
            acc2[i][0] = fmaf(a.y, w1.x, acc2[i][0]);
            acc2[i][0] = fmaf(a.z, w2.x, acc2[i][0]);
            acc2[i][0] = fmaf(a.w, w3.x, acc2[i][0]);
            acc2[i][1] = fmaf(a.x, w0.y, acc2[i][1]);
            acc2[i][1] = fmaf(a.y, w1.y, acc2[i][1]);
            acc2[i][1] = fmaf(a.z, w2.y, acc2[i][1]);
            acc2[i][1] = fmaf(a.w, w3.y, acc2[i][1]);
            acc2[i][2] = fmaf(a.x, w0.z, acc2[i][2]);
            acc2[i][2] = fmaf(a.y, w1.z, acc2[i][2]);
            acc2[i][2] = fmaf(a.z, w2.z, acc2[i][2]);
            acc2[i][2] = fmaf(a.w, w3.z, acc2[i][2]);
            acc2[i][3] = fmaf(a.x, w0.w, acc2[i][3]);
            acc2[i][3] = fmaf(a.y, w1.w, acc2[i][3]);
            acc2[i][3] = fmaf(a.z, w2.w, acc2[i][3]);
            acc2[i][3] = fmaf(a.w, w3.w, acc2[i][3]);
        }
    }

    // store attn_out
    #pragma unroll
    for (int i = 0; i < 4; ++i) {
        int r = r0 + i;
        float m = m_s[r];
        float4 v = make_float4(acc2[i][0] * m, acc2[i][1] * m,
                               acc2[i][2] * m, acc2[i][3] * m);
        *(float4*)(attn_out + base + (long)r * D + c0) = v;
    }
}

extern "C" void kernel_launch(void* const* d_in, const int* in_sizes, int n_in,
                              void* d_out, int out_size)
{
    const float* Q    = (const float*)d_in[0];
    const float* K    = (const float*)d_in[1];
    const float* we   = (const float*)d_in[2];
    const float* wr   = (const float*)d_in[3];
    const float* mask = (const float*)d_in[4];
    const float* W    = (const float*)d_in[5];
    const float* b    = (const float*)d_in[6];
    const float* Lam  = (const float*)d_in[7];

    float* out = (float*)d_out;
    const long nAttn = 4L * 12 * 4096 * 64;   // 12,582,912
    const long nSc   = 4L * 12 * 4096 * 32;   //  6,291,456
    const long nW0   = 12L * 64 * 32;         //     24,576
    float* attn = out;
    float* esc  = attn + nAttn;
    float* rsc  = esc + nSc;
    float* we0o = rsc + nSc;
    float* wr0o = we0o + nW0;
    float* qo   = wr0o + nW0;
    float* ko   = qo + nAttn;
    float* lo   = ko + nAttn;

    // passthrough outputs (we[0], wr[0] are contiguous leading slices; Lambda whole)
    cudaMemcpyAsync(we0o, we,  nW0 * sizeof(float), cudaMemcpyDeviceToDevice);
    cudaMemcpyAsync(wr0o, wr,  nW0 * sizeof(float), cudaMemcpyDeviceToDevice);
    cudaMemcpyAsync(lo,   Lam, 12L * 32 * sizeof(float), cudaMemcpyDeviceToDevice);

    // smem: q_s/sc_s(alias) + k_s + sw + wt(WTP) + b + mask  (~69 KB -> 3 CTAs/SM)
    const size_t shmem = (size_t)(2 * TILE_N * PAD + 64 * 64 + 64 * WTP + 64 + 64) * sizeof(float);
    cudaFuncSetAttribute(pca_kernel, cudaFuncAttributeMaxDynamicSharedMemorySize, (int)shmem);

    dim3 grid(4096 / TILE_N, 12, 4);
    pca_kernel<<<grid, 256, shmem>>>(Q, K, we, wr, mask, W, b,
                                     attn, esc, rsc, qo, ko);
}

// round 16
// speedup vs baseline: 1.3402x; 1.0832x over previous
#include <cuda_runtime.h>

// PrimalCosAttention: B=4,H=12,N=4096,D=64,E=32
// out layout (floats):
//  attn   [B,H,N,D]  @ 0           (12,582,912)
//  escore [B,H,N,E]  @ 12,582,912  ( 6,291,456)
//  rscore [B,H,N,E]  @ 18,874,368  ( 6,291,456)
//  we0    [H,D,E]    @ 25,165,824  (    24,576)
//  wr0    [H,D,E]    @ 25,190,400  (    24,576)
//  queries[B,H,N,D]  @ 25,214,976  (12,582,912)
//  keys   [B,H,N,D]  @ 37,797,888  (12,582,912)
//  Lambda [H,E]      @ 50,380,800  (       384)

#define TILE_N 64
#define PAD 68        // row stride (floats) for q/k/score tiles; 16B-aligned
#define WTP 68        // row stride (floats) for transposed-W tile; 16B-aligned

// row swizzle: element (r,k) stored at column (k + (r&8)) & 63.
// Kills the 2-way bank conflict on A-loads (4-row stride ≡ 16 banks).
__device__ __forceinline__ int SW(int r, int k) { return (k + (r & 8)) & 63; }

__global__ __launch_bounds__(256, 4)
void pca_kernel(const float* __restrict__ Q, const float* __restrict__ K,
                const float* __restrict__ we, const float* __restrict__ wr,
                const float* __restrict__ mask, const float* __restrict__ W,
                const float* __restrict__ bias,
                float* __restrict__ attn_out, float* __restrict__ escore,
                float* __restrict__ rscore, float* __restrict__ queries,
                float* __restrict__ keys)
{
    const int H = 12, N = 4096, D = 64, E = 32;

    extern __shared__ float smem[];
    float* q_s  = smem;                    // [64][PAD] normalized Q tile (swizzled cols)
    float* sc_s = smem;                    // ALIAS: score tile reuses q_s after phase 2
    float* k_s  = q_s  + TILE_N * PAD;     // [64][PAD] normalized K tile (swizzled cols)
    float* wt   = k_s;                     // ALIAS: wt[e][d]=W[d][e] reuses k_s after phase 2
    float* sw   = k_s  + TILE_N * PAD;     // [64][64]: cols 0..31 = we0[h], 32..63 = wr0[h] (k-major)
    float* b_s  = sw   + 64 * 64;          // [64]
    float* m_s  = b_s  + 64;               // [64] mask tile

    const int tile = blockIdx.x;
    const int h    = blockIdx.y;
    const int bq   = blockIdx.z;
    const int n0   = tile * TILE_N;
    const int t    = threadIdx.x;          // 0..255
    const int lane = t & 31;
    const int wp   = t >> 5;               // warp 0..7

    const long base = ((long)(bq * H + h) * N + n0) * D;

    // ---- load phase-2 weights (sw only; wt restaged into dead k_s later) ----
    const float* weh = we + (long)h * D * E;
    const float* wrh = wr + (long)h * D * E;
    for (int i = t; i < 64 * 64; i += 256) {
        int r = i >> 6, c = i & 63;
        sw[i] = (c < 32) ? weh[r * E + c] : wrh[r * E + (c - 32)];
    }
    if (t < 64) {
        b_s[t] = bias[t];
        m_s[t] = mask[(long)bq * N + n0 + t];
    }

    // ---- phase 1: L2 normalize. Warp: 4 rows/iter, 8 lanes/row, 8 floats/lane.
    {
        const int subrow = lane >> 3;
        const int sub    = lane & 7;
        #pragma unroll
        for (int it = 0; it < 2; ++it) {
            int r = it * 32 + wp * 4 + subrow;
            long g = base + (long)r * D + sub * 8;
            float4 qa = *(const float4*)(Q + g);
            float4 qb = *(const float4*)(Q + g + 4);
            float4 ka = *(const float4*)(K + g);
            float4 kb = *(const float4*)(K + g + 4);
            float sq = qa.x*qa.x + qa.y*qa.y + qa.z*qa.z + qa.w*qa.w
                     + qb.x*qb.x + qb.y*qb.y + qb.z*qb.z + qb.w*qb.w;
            float sk = ka.x*ka.x + ka.y*ka.y + ka.z*ka.z + ka.w*ka.w
                     + kb.x*kb.x + kb.y*kb.y + kb.z*kb.z + kb.w*kb.w;
            #pragma unroll
            for (int o = 4; o > 0; o >>= 1) {
                sq += __shfl_xor_sync(0xffffffffu, sq, o);
                sk += __shfl_xor_sync(0xffffffffu, sk, o);
            }
            float iq = rsqrtf(fmaxf(sq, 1e-24f));
            float ik = rsqrtf(fmaxf(sk, 1e-24f));
            qa.x *= iq; qa.y *= iq; qa.z *= iq; qa.w *= iq;
            qb.x *= iq; qb.y *= iq; qb.z *= iq; qb.w *= iq;
            ka.x *= ik; ka.y *= ik; ka.z *= ik; ka.w *= ik;
            kb.x *= ik; kb.y *= ik; kb.z *= ik; kb.w *= ik;
            int col = (sub * 8 + (r & 8)) & 63;
            *(float4*)(q_s + r * PAD + col)     = qa;
            *(float4*)(q_s + r * PAD + col + 4) = qb;
            *(float4*)(k_s + r * PAD + col)     = ka;
            *(float4*)(k_s + r * PAD + col + 4) = kb;
            *(float4*)(queries + g)     = qa;
            *(float4*)(queries + g + 4) = qb;
            *(float4*)(keys + g)        = ka;
            *(float4*)(keys + g + 4)    = kb;
        }
    }
    __syncthreads();

    // ---- phase 2: score GEMM.  [64 x 64]; cols 0..31 escore (A=qn), 32..63 rscore (A=kn)
    // warp shape: 8 tx (32 cols) x 4 ty (16 rows) -> weight LDS = 128B contiguous
    const int tx = (lane & 7) | ((wp & 1) << 3);   // 0..15
    const int ty = (lane >> 3) | ((wp >> 1) << 2); // 0..15
    const int c0 = tx * 4;
    const int r0 = ty * 4;
    const float* At = (tx < 8) ? q_s : k_s;

    float acc[4][4];
    #pragma unroll
    for (int i = 0; i < 4; ++i)
        #pragma unroll
        for (int jj = 0; jj < 4; ++jj) acc[i][jj] = 0.0f;

    #pragma unroll 4
    for (int kk = 0; kk < 16; ++kk) {
        const int k4 = kk << 2;
        const float4 w0 = *(const float4*)(sw + (k4 + 0) * 64 + c0);
        const float4 w1 = *(const float4*)(sw + (k4 + 1) * 64 + c0);
        const float4 w2 = *(const float4*)(sw + (k4 + 2) * 64 + c0);
        const float4 w3 = *(const float4*)(sw + (k4 + 3) * 64 + c0);
        #pragma unroll
        for (int i = 0; i < 4; ++i) {
            const int r = r0 + i;
            const float4 a = *(const float4*)(At + r * PAD + SW(r, k4));
            acc[i][0] = fmaf(a.x, w0.x, acc[i][0]);
            acc[i][0] = fmaf(a.y, w1.x, acc[i][0]);
            acc[i][0] = fmaf(a.z, w2.x, acc[i][0]);
            acc[i][0] = fmaf(a.w, w3.x, acc[i][0]);
            acc[i][1] = fmaf(a.x, w0.y, acc[i][1]);
            acc[i][1] = fmaf(a.y, w1.y, acc[i][1]);
            acc[i][1] = fmaf(a.z, w2.y, acc[i][1]);
            acc[i][1] = fmaf(a.w, w3.y, acc[i][1]);
            acc[i][2] = fmaf(a.x, w0.z, acc[i][2]);
            acc[i][2] = fmaf(a.y, w1.z, acc[i][2]);
            acc[i][2] = fmaf(a.z, w2.z, acc[i][2]);
            acc[i][2] = fmaf(a.w, w3.z, acc[i][2]);
            acc[i][3] = fmaf(a.x, w0.w, acc[i][3]);
            acc[i][3] = fmaf(a.y, w1.w, acc[i][3]);
            acc[i][3] = fmaf(a.z, w2.w, acc[i][3]);
            acc[i][3] = fmaf(a.w, w3.w, acc[i][3]);
        }
    }

    // write score to gmem (escore / rscore) — no smem involved, safe before barrier
    {
        const long so = ((long)(bq * H + h) * N + n0) * E;
        float* sout = (tx < 8) ? (escore + so) : (rscore + so);
        const int ce = c0 & 31;
        #pragma unroll
        for (int i = 0; i < 4; ++i) {
            int r = r0 + i;
            *(float4*)(sout + (long)r * E + ce) =
                make_float4(acc[i][0], acc[i][1], acc[i][2], acc[i][3]);
        }
    }

    // reads of q_s/k_s done -> overwrite q_s with score tile, k_s with wt
    __syncthreads();
    #pragma unroll
    for (int i = 0; i < 4; ++i) {
        int r = r0 + i;
        *(float4*)(sc_s + r * PAD + SW(r, c0)) =
            make_float4(acc[i][0], acc[i][1], acc[i][2], acc[i][3]);
    }
    // restage wt[e][d] = W[d][e] into dead k_s: COALESCED gmem read (16KB/CTA,
    // L2-resident), transpose on the STS side (4-way conflict on 128 STS — ~0.5us total)
    for (int i = t; i < 64 * 64; i += 256) {
        int d = i >> 6, e = i & 63;
        wt[e * WTP + d] = W[i];
    }
    __syncthreads();

    // ---- phase 3: attn = score @ W^T + b, * mask.  [64 x 64], K = 64 (e)
    float acc2[4][4];
    #pragma unroll
    for (int i = 0; i < 4; ++i) {
        acc2[i][0] = b_s[c0 + 0];
        acc2[i][1] = b_s[c0 + 1];
        acc2[i][2] = b_s[c0 + 2];
        acc2[i][3] = b_s[c0 + 3];
    }

    #pragma unroll 4
    for (int kk = 0; kk < 16; ++kk) {
        const int e4 = kk << 2;
        const float4 w0 = *(const float4*)(wt + (e4 + 0) * WTP + c0);
        const float4 w1 = *(const float4*)(wt + (e4 + 1) * WTP + c0);
        const float4 w2 = *(const float4*)(wt + (e4 + 2) * WTP + c0);
        const float4 w3 = *(const float4*)(wt + (e4 + 3) * WTP + c0);
        #pragma unroll
        for (int i = 0; i < 4; ++i) {
            const int r = r0 + i;
            const float4 a = *(const float4*)(sc_s + r * PAD + SW(r, e4));
            acc2[i][0] = fmaf(a.x, w0.x, acc2[i][0]);
            acc2[i][0] = fmaf(a.y, w1.x, acc2[i][0]);
            acc2[i][0] = fmaf(a.z, w2.x, acc2[i][0]);
            acc2[i][0] = fmaf(a.w, w3.x, acc2[i][0]);
            acc2[i][1] = fmaf(a.x, w0.y, acc2[i][1]);
            acc2[i][1] = fmaf(a.y, w1.y, acc2[i][1]);
            acc2[i][1] = fmaf(a.z, w2.y, acc2[i][1]);
            acc2[i][1] = fmaf(a.w, w3.y, acc2[i][1]);
            acc2[i][2] = fmaf(a.x, w0.z, acc2[i][2]);
            acc2[i][2] = fmaf(a.y, w1.z, acc2[i][2]);
            acc2[i][2] = fmaf(a.z, w2.z, acc2[i][2]);
            acc2[i][2] = fmaf(a.w, w3.z, acc2[i][2]);
            acc2[i][3] = fmaf(a.x, w0.w, acc2[i][3]);
            acc2[i][3] = fmaf(a.y, w1.w, acc2[i][3]);
            acc2[i][3] = fmaf(a.z, w2.w, acc2[i][3]);
            acc2[i][3] = fmaf(a.w, w3.w, acc2[i][3]);
        }
    }

    // store attn_out
    #pragma unroll
    for (int i = 0; i < 4; ++i) {
        int r = r0 + i;
        float m = m_s[r];
        float4 v = make_float4(acc2[i][0] * m, acc2[i][1] * m,
                               acc2[i][2] * m, acc2[i][3] * m);
        *(float4*)(attn_out + base + (long)r * D + c0) = v;
    }
}

extern "C" void kernel_launch(void* const* d_in, const int* in_sizes, int n_in,
                              void* d_out, int out_size)
{
    const float* Q    = (const float*)d_in[0];
    const float* K    = (const float*)d_in[1];
    const float* we   = (const float*)d_in[2];
    const float* wr   = (const float*)d_in[3];
    const float* mask = (const float*)d_in[4];
    const float* W    = (const float*)d_in[5];
    const float* b    = (const float*)d_in[6];
    const float* Lam  = (const float*)d_in[7];

    float* out = (float*)d_out;
    const long nAttn = 4L * 12 * 4096 * 64;   // 12,582,912
    const long nSc   = 4L * 12 * 4096 * 32;   //  6,291,456
    const long nW0   = 12L * 64 * 32;         //     24,576
    float* attn = out;
    float* esc  = attn + nAttn;
    float* rsc  = esc + nSc;
    float* we0o = rsc + nSc;
    float* wr0o = we0o + nW0;
    float* qo   = wr0o + nW0;
    float* ko   = qo + nAttn;
    float* lo   = ko + nAttn;

    // passthrough outputs (we[0], wr[0] are contiguous leading slices; Lambda whole)
    cudaMemcpyAsync(we0o, we,  nW0 * sizeof(float), cudaMemcpyDeviceToDevice);
    cudaMemcpyAsync(wr0o, wr,  nW0 * sizeof(float), cudaMemcpyDeviceToDevice);
    cudaMemcpyAsync(lo,   Lam, 12L * 32 * sizeof(float), cudaMemcpyDeviceToDevice);

    // smem: q_s/sc_s(alias) + k_s/wt(alias, WTP=PAD) + sw + b + mask = 51.7 KB -> 4 CTAs/SM
    const size_t shmem = (size_t)(2 * TILE_N * PAD + 64 * 64 + 64 + 64) * sizeof(float);
    cudaFuncSetAttribute(pca_kernel, cudaFuncAttributeMaxDynamicSharedMemorySize, (int)shmem);

    dim3 grid(4096 / TILE_N, 12, 4);
    pca_kernel<<<grid, 256, shmem>>>(Q, K, we, wr, mask, W, b,
                                     attn, esc, rsc, qo, ko);
}

// round 17
// speedup vs baseline: 1.3608x; 1.0153x over previous
#include <cuda_runtime.h>

// PrimalCosAttention: B=4,H=12,N=4096,D=64,E=32
// out layout (floats):
//  attn   [B,H,N,D]  @ 0           (12,582,912)
//  escore [B,H,N,E]  @ 12,582,912  ( 6,291,456)
//  rscore [B,H,N,E]  @ 18,874,368  ( 6,291,456)
//  we0    [H,D,E]    @ 25,165,824  (    24,576)
//  wr0    [H,D,E]    @ 25,190,400  (    24,576)
//  queries[B,H,N,D]  @ 25,214,976  (12,582,912)
//  keys   [B,H,N,D]  @ 37,797,888  (12,582,912)
//  Lambda [H,E]      @ 50,380,800  (       384)

#define TILE_N 64
#define PAD 68        // row stride (floats) for q/k/score tiles; 16B-aligned
#define WTP 68        // row stride (floats) for transposed-W tile; 16B-aligned

typedef unsigned long long u64;

// row swizzle: element (r,k) stored at column (k + (r&8)) & 63.
// Kills the 2-way bank conflict on A-loads (4-row stride ≡ 16 banks).
__device__ __forceinline__ int SW(int r, int k) { return (k + (r & 8)) & 63; }

// packed f32x2 fma: d.lo += a.lo*b.lo ; d.hi += a.hi*b.hi   (sm_103a)
__device__ __forceinline__ void ffma2(u64 &d, u64 a, u64 b) {
    asm("fma.rn.f32x2 %0, %1, %2, %0;" : "+l"(d) : "l"(a), "l"(b));
}
// duplicate a scalar into both halves of a 64-bit packed reg
__device__ __forceinline__ u64 dup2(float x) {
    u64 r;
    asm("mov.b64 %0, {%1, %1};" : "=l"(r) : "f"(x));
    return r;
}
__device__ __forceinline__ float2 unpk(u64 v) { return *(float2*)&v; }

__global__ __launch_bounds__(256, 4)
void pca_kernel(const float* __restrict__ Q, const float* __restrict__ K,
                const float* __restrict__ we, const float* __restrict__ wr,
                const float* __restrict__ mask, const float* __restrict__ W,
                const float* __restrict__ bias,
                float* __restrict__ attn_out, float* __restrict__ escore,
                float* __restrict__ rscore, float* __restrict__ queries,
                float* __restrict__ keys)
{
    const int H = 12, N = 4096, D = 64, E = 32;

    extern __shared__ float smem[];
    float* q_s  = smem;                    // [64][PAD] normalized Q tile (swizzled cols)
    float* sc_s = smem;                    // ALIAS: score tile reuses q_s after phase 2
    float* k_s  = q_s  + TILE_N * PAD;     // [64][PAD] normalized K tile (swizzled cols)
    float* wt   = k_s;                     // ALIAS: wt[e][d]=W[d][e] reuses k_s after phase 2
    float* sw   = k_s  + TILE_N * PAD;     // [64][64]: cols 0..31 = we0[h], 32..63 = wr0[h] (k-major)
    float* b_s  = sw   + 64 * 64;          // [64]
    float* m_s  = b_s  + 64;               // [64] mask tile

    const int tile = blockIdx.x;
    const int h    = blockIdx.y;
    const int bq   = blockIdx.z;
    const int n0   = tile * TILE_N;
    const int t    = threadIdx.x;          // 0..255
    const int lane = t & 31;
    const int wp   = t >> 5;               // warp 0..7

    const long base = ((long)(bq * H + h) * N + n0) * D;

    // ---- load phase-2 weights (sw only; wt restaged into dead k_s later) ----
    const float* weh = we + (long)h * D * E;
    const float* wrh = wr + (long)h * D * E;
    for (int i = t; i < 64 * 64; i += 256) {
        int r = i >> 6, c = i & 63;
        sw[i] = (c < 32) ? weh[r * E + c] : wrh[r * E + (c - 32)];
    }
    if (t < 64) {
        b_s[t] = bias[t];
        m_s[t] = mask[(long)bq * N + n0 + t];
    }

    // ---- phase 1: L2 normalize. Warp: 4 rows/iter, 8 lanes/row, 8 floats/lane.
    {
        const int subrow = lane >> 3;
        const int sub    = lane & 7;
        #pragma unroll
        for (int it = 0; it < 2; ++it) {
            int r = it * 32 + wp * 4 + subrow;
            long g = base + (long)r * D + sub * 8;
            float4 qa = *(const float4*)(Q + g);
            float4 qb = *(const float4*)(Q + g + 4);
            float4 ka = *(const float4*)(K + g);
            float4 kb = *(const float4*)(K + g + 4);
            float sq = qa.x*qa.x + qa.y*qa.y + qa.z*qa.z + qa.w*qa.w
                     + qb.x*qb.x + qb.y*qb.y + qb.z*qb.z + qb.w*qb.w;
            float sk = ka.x*ka.x + ka.y*ka.y + ka.z*ka.z + ka.w*ka.w
                     + kb.x*kb.x + kb.y*kb.y + kb.z*kb.z + kb.w*kb.w;
            #pragma unroll
            for (int o = 4; o > 0; o >>= 1) {
                sq += __shfl_xor_sync(0xffffffffu, sq, o);
                sk += __shfl_xor_sync(0xffffffffu, sk, o);
            }
            float iq = rsqrtf(fmaxf(sq, 1e-24f));
            float ik = rsqrtf(fmaxf(sk, 1e-24f));
            qa.x *= iq; qa.y *= iq; qa.z *= iq; qa.w *= iq;
            qb.x *= iq; qb.y *= iq; qb.z *= iq; qb.w *= iq;
            ka.x *= ik; ka.y *= ik; ka.z *= ik; ka.w *= ik;
            kb.x *= ik; kb.y *= ik; kb.z *= ik; kb.w *= ik;
            int col = (sub * 8 + (r & 8)) & 63;
            *(float4*)(q_s + r * PAD + col)     = qa;
            *(float4*)(q_s + r * PAD + col + 4) = qb;
            *(float4*)(k_s + r * PAD + col)     = ka;
            *(float4*)(k_s + r * PAD + col + 4) = kb;
            *(float4*)(queries + g)     = qa;
            *(float4*)(queries + g + 4) = qb;
            *(float4*)(keys + g)        = ka;
            *(float4*)(keys + g + 4)    = kb;
        }
    }
    __syncthreads();

    // ---- phase 2: score GEMM.  [64 x 64]; cols 0..31 escore (A=qn), 32..63 rscore (A=kn)
    // warp shape: 8 tx (32 cols) x 4 ty (16 rows) -> weight LDS = 128B contiguous
    const int tx = (lane & 7) | ((wp & 1) << 3);   // 0..15
    const int ty = (lane >> 3) | ((wp >> 1) << 2); // 0..15
    const int c0 = tx * 4;
    const int r0 = ty * 4;
    const float* At = (tx < 8) ? q_s : k_s;

    // accp[i][jp] = packed (col c0+2jp, c0+2jp+1) accumulator for row r0+i
    u64 accp[4][2];
    #pragma unroll
    for (int i = 0; i < 4; ++i) { accp[i][0] = 0ull; accp[i][1] = 0ull; }

    #pragma unroll 4
    for (int kk = 0; kk < 16; ++kk) {
        const int k4 = kk << 2;
        const ulonglong2 w0 = *(const ulonglong2*)(sw + (k4 + 0) * 64 + c0);
        const ulonglong2 w1 = *(const ulonglong2*)(sw + (k4 + 1) * 64 + c0);
        const ulonglong2 w2 = *(const ulonglong2*)(sw + (k4 + 2) * 64 + c0);
        const ulonglong2 w3 = *(const ulonglong2*)(sw + (k4 + 3) * 64 + c0);
        #pragma unroll
        for (int i = 0; i < 4; ++i) {
            const int r = r0 + i;
            const float4 a = *(const float4*)(At + r * PAD + SW(r, k4));
            const u64 ax = dup2(a.x), ay = dup2(a.y), az = dup2(a.z), aw = dup2(a.w);
            ffma2(accp[i][0], ax, w0.x);
            ffma2(accp[i][0], ay, w1.x);
            ffma2(accp[i][0], az, w2.x);
            ffma2(accp[i][0], aw, w3.x);
            ffma2(accp[i][1], ax, w0.y);
            ffma2(accp[i][1], ay, w1.y);
            ffma2(accp[i][1], az, w2.y);
            ffma2(accp[i][1], aw, w3.y);
        }
    }

    // write score to gmem (escore / rscore) — no smem involved, safe before barrier
    {
        const long so = ((long)(bq * H + h) * N + n0) * E;
        float* sout = (tx < 8) ? (escore + so) : (rscore + so);
        const int ce = c0 & 31;
        #pragma unroll
        for (int i = 0; i < 4; ++i) {
            int r = r0 + i;
            float2 lo = unpk(accp[i][0]), hi = unpk(accp[i][1]);
            *(float4*)(sout + (long)r * E + ce) = make_float4(lo.x, lo.y, hi.x, hi.y);
        }
    }

    // reads of q_s/k_s done -> overwrite q_s with score tile, k_s with wt
    __syncthreads();
    #pragma unroll
    for (int i = 0; i < 4; ++i) {
        int r = r0 + i;
        float2 lo = unpk(accp[i][0]), hi = unpk(accp[i][1]);
        *(float4*)(sc_s + r * PAD + SW(r, c0)) = make_float4(lo.x, lo.y, hi.x, hi.y);
    }
    // restage wt[e][d] = W[d][e] into dead k_s: COALESCED gmem read (16KB/CTA,
    // L2-resident), transpose on the STS side (4-way conflict on 128 STS)
    for (int i = t; i < 64 * 64; i += 256) {
        int d = i >> 6, e = i & 63;
        wt[e * WTP + d] = W[i];
    }
    __syncthreads();

    // ---- phase 3: attn = score @ W^T + b, * mask.  [64 x 64], K = 64 (e)
    u64 acc2[4][2];
    {
        const u64 bp0 = *(const u64*)(b_s + c0);
        const u64 bp1 = *(const u64*)(b_s + c0 + 2);
        #pragma unroll
        for (int i = 0; i < 4; ++i) { acc2[i][0] = bp0; acc2[i][1] = bp1; }
    }

    #pragma unroll 4
    for (int kk = 0; kk < 16; ++kk) {
        const int e4 = kk << 2;
        const ulonglong2 w0 = *(const ulonglong2*)(wt + (e4 + 0) * WTP + c0);
        const ulonglong2 w1 = *(const ulonglong2*)(wt + (e4 + 1) * WTP + c0);
        const ulonglong2 w2 = *(const ulonglong2*)(wt + (e4 + 2) * WTP + c0);
        const ulonglong2 w3 = *(const ulonglong2*)(wt + (e4 + 3) * WTP + c0);
        #pragma unroll
        for (int i = 0; i < 4; ++i) {
            const int r = r0 + i;
            const float4 a = *(const float4*)(sc_s + r * PAD + SW(r, e4));
            const u64 ax = dup2(a.x), ay = dup2(a.y), az = dup2(a.z), aw = dup2(a.w);
            ffma2(acc2[i][0], ax, w0.x);
            ffma2(acc2[i][0], ay, w1.x);
            ffma2(acc2[i][0], az, w2.x);
            ffma2(acc2[i][0], aw, w3.x);
            ffma2(acc2[i][1], ax, w0.y);
            ffma2(acc2[i][1], ay, w1.y);
            ffma2(acc2[i][1], az, w2.y);
            ffma2(acc2[i][1], aw, w3.y);
        }
    }

    // store attn_out (apply mask)
    #pragma unroll
    for (int i = 0; i < 4; ++i) {
        int r = r0 + i;
        float m = m_s[r];
        float2 lo = unpk(acc2[i][0]), hi = unpk(acc2[i][1]);
        float4 v = make_float4(lo.x * m, lo.y * m, hi.x * m, hi.y * m);
        *(float4*)(attn_out + base + (long)r * D + c0) = v;
    }
}

extern "C" void kernel_launch(void* const* d_in, const int* in_sizes, int n_in,
                              void* d_out, int out_size)
{
    const float* Q    = (const float*)d_in[0];
    const float* K    = (const float*)d_in[1];
    const float* we   = (const float*)d_in[2];
    const float* wr   = (const float*)d_in[3];
    const float* mask = (const float*)d_in[4];
    const float* W    = (const float*)d_in[5];
    const float* b    = (const float*)d_in[6];
    const float* Lam  = (const float*)d_in[7];

    float* out = (float*)d_out;
    const long nAttn = 4L * 12 * 4096 * 64;   // 12,582,912
    const long nSc   = 4L * 12 * 4096 * 32;   //  6,291,456
    const long nW0   = 12L * 64 * 32;         //     24,576
    float* attn = out;
    float* esc  = attn + nAttn;
    float* rsc  = esc + nSc;
    float* we0o = rsc + nSc;
    float* wr0o = we0o + nW0;
    float* qo   = wr0o + nW0;
    float* ko   = qo + nAttn;
    float* lo   = ko + nAttn;

    // passthrough outputs (we[0], wr[0] are contiguous leading slices; Lambda whole)
    cudaMemcpyAsync(we0o, we,  nW0 * sizeof(float), cudaMemcpyDeviceToDevice);
    cudaMemcpyAsync(wr0o, wr,  nW0 * sizeof(float), cudaMemcpyDeviceToDevice);
    cudaMemcpyAsync(lo,   Lam, 12L * 32 * sizeof(float), cudaMemcpyDeviceToDevice);

    // smem: q_s/sc_s(alias) + k_s/wt(alias, WTP=PAD) + sw + b + mask = 51.7 KB -> 4 CTAs/SM
    const size_t shmem = (size_t)(2 * TILE_N * PAD + 64 * 64 + 64 + 64) * sizeof(float);
    cudaFuncSetAttribute(pca_kernel, cudaFuncAttributeMaxDynamicSharedMemorySize, (int)shmem);

    dim3 grid(4096 / TILE_N, 12, 4);
    pca_kernel<<<grid, 256, shmem>>>(Q, K, we, wr, mask, W, b,
                                     attn, esc, rsc, qo, ko);
}